// round 13
// baseline (speedup 1.0000x reference)
#include <cuda_runtime.h>
#include <cuda_bf16.h>
#include <cstdint>
#include <cstddef>

#define NN 8192
#define DIM 256

// ---------------- device-global scratch ----------------
__device__ float g_Wh[NN * DIM];
__device__ float g_H[NN * DIM];
__device__ float g_s[NN];
__device__ float g_d[NN];
__device__ float4 g_EEpG[NN];                 // (E, Ep, G, qs) per node
__device__ float2 g_FFp[NN];                  // (F, Fp) per node
__device__ uint8_t g_Bh8[DIM * NN];           // B16 high limb (s8), k-permuted
__device__ uint8_t g_Bl8[DIM * NN];           // B16 low  limb (s8, debiased), k-permuted
__device__ float g_colmax[DIM];               // per-dim absmax of Wh
__device__ uint32_t g_adjP[NN * (NN / 32)];   // bit-packed adjacency

// ---------------- helpers ----------------
__device__ __forceinline__ void cpasync16(uint32_t saddr, const void* g) {
    asm volatile("cp.async.cg.shared.global [%0], [%1], 16;" :: "r"(saddr), "l"(g));
}
__device__ __forceinline__ void cpasync_commit() { asm volatile("cp.async.commit_group;"); }
__device__ __forceinline__ void cpasync_wait0() { asm volatile("cp.async.wait_group 0;"); }
__device__ __forceinline__ float elu1(float x) { return x > 0.0f ? x : expm1f(x); }

// int8 tensor-core MMA, K=32
__device__ __forceinline__ void imma(int* c, const uint32_t* a, const uint32_t* b) {
    asm volatile(
        "mma.sync.aligned.m16n8k32.row.col.s32.s8.s8.s32 "
        "{%0,%1,%2,%3}, {%4,%5,%6,%7}, {%8,%9}, {%0,%1,%2,%3};"
        : "+r"(c[0]), "+r"(c[1]), "+r"(c[2]), "+r"(c[3])
        : "r"(a[0]), "r"(a[1]), "r"(a[2]), "r"(a[3]), "r"(b[0]), "r"(b[1]));
}

// f32x2 helpers for the feature GEMM
__device__ __forceinline__ unsigned long long pk2(float lo, float hi) {
    unsigned long long r;
    asm("mov.b64 %0, {%1, %2};" : "=l"(r) : "f"(lo), "f"(hi));
    return r;
}
__device__ __forceinline__ void upk2(unsigned long long v, float& lo, float& hi) {
    asm("mov.b64 {%0, %1}, %2;" : "=f"(lo), "=f"(hi) : "l"(v));
}
__device__ __forceinline__ void fma2(unsigned long long& acc, unsigned long long a,
                                     unsigned long long b) {
    asm("fma.rn.f32x2 %0, %1, %2, %0;" : "+l"(acc) : "l"(a), "l"(b));
}

// k-permutation within a 32-byte group: chunk c (4B) -> position 2c (c<4) / 2(c-4)+1
__device__ __forceinline__ int kperm(int u) {   // u = 4-byte chunk index within row
    int g = u >> 3, c = u & 7;
    int npos = (c < 4) ? (2 * c) : (2 * c - 7);
    return g * 32 + npos * 4;
}

// ================= adj bit-pack =================
__global__ __launch_bounds__(256) void pack_adj_kernel(const int* __restrict__ adj,
                                                       uint32_t* __restrict__ adjP) {
    int warpId = (blockIdx.x * 256 + threadIdx.x) >> 5;
    int lane = threadIdx.x & 31;
    const int* base = adj + (size_t)warpId * 1024;
    uint32_t w = 0;
#pragma unroll
    for (int k = 0; k < 32; ++k) {
        uint32_t b = __ballot_sync(0xffffffffu, base[k * 32 + lane] != 0);
        if (lane == k) w = b;
    }
    adjP[(size_t)warpId * 32 + lane] = w;
}

// ================= Wh = X @ W (SIMT f32x2) =================
constexpr int GW_BM = 64, GW_BK = 32, GW_NT = 256, GW_ASTR = 68;

__device__ __forceinline__ void mm_block(const float* As, const float* Bs,
                                         unsigned long long acc[32], int r0, int c0) {
#pragma unroll 8
    for (int kk = 0; kk < GW_BK; ++kk) {
        float4 a0 = *reinterpret_cast<const float4*>(As + kk * GW_ASTR + r0);
        float4 a1 = *reinterpret_cast<const float4*>(As + kk * GW_ASTR + r0 + 4);
        float4 b0 = *reinterpret_cast<const float4*>(Bs + kk * DIM + c0);
        float4 b1 = *reinterpret_cast<const float4*>(Bs + kk * DIM + c0 + 4);
        unsigned long long ap[4];
        ap[0] = pk2(a0.x, a0.y); ap[1] = pk2(a0.z, a0.w);
        ap[2] = pk2(a1.x, a1.y); ap[3] = pk2(a1.z, a1.w);
        float bv[8] = {b0.x, b0.y, b0.z, b0.w, b1.x, b1.y, b1.z, b1.w};
#pragma unroll
        for (int n = 0; n < 8; ++n) {
            unsigned long long bb = pk2(bv[n], bv[n]);
#pragma unroll
            for (int m = 0; m < 4; ++m) fma2(acc[m * 8 + n], ap[m], bb);
        }
    }
}

__global__ __launch_bounds__(GW_NT) void gemm_wh_kernel(const float* __restrict__ X,
                                                        const float* __restrict__ W,
                                                        float* __restrict__ out) {
    __shared__ float As[GW_BK * GW_ASTR];
    __shared__ float Bs[GW_BK * DIM];
    int t = threadIdx.x;
    int i0 = blockIdx.x * GW_BM;
    int tA_r = t >> 2, tA_c = t & 3;
    int tr = t >> 5, tc = t & 31;
    int r0 = tr * 8, c0 = tc * 8;
    unsigned long long acc[32];
#pragma unroll
    for (int i = 0; i < 32; ++i) acc[i] = 0ull;

    for (int p = 0; p < DIM / GW_BK; ++p) {
        int k0 = p * GW_BK;
        const float4* xsrc = reinterpret_cast<const float4*>(
            X + (size_t)(i0 + tA_r) * DIM + k0 + tA_c * 8);
        float4 x0 = xsrc[0], x1 = xsrc[1];
        __syncthreads();
        float xv[8] = {x0.x, x0.y, x0.z, x0.w, x1.x, x1.y, x1.z, x1.w};
#pragma unroll
        for (int u = 0; u < 8; ++u) As[(tA_c * 8 + u) * GW_ASTR + tA_r] = xv[u];
        const float4* wsrc = reinterpret_cast<const float4*>(W + (size_t)k0 * DIM);
        float4* bdst = reinterpret_cast<float4*>(Bs);
#pragma unroll
        for (int k = 0; k < 8; ++k) bdst[t + k * GW_NT] = wsrc[t + k * GW_NT];
        __syncthreads();
        mm_block(As, Bs, acc, r0, c0);
    }
#pragma unroll
    for (int m = 0; m < 4; ++m) {
        int ra = r0 + 2 * m;
        float oa[8], ob[8];
#pragma unroll
        for (int n = 0; n < 8; ++n) upk2(acc[m * 8 + n], oa[n], ob[n]);
        float4* da = reinterpret_cast<float4*>(out + (size_t)(i0 + ra) * DIM + c0);
        float4* db = reinterpret_cast<float4*>(out + (size_t)(i0 + ra + 1) * DIM + c0);
        da[0] = make_float4(oa[0], oa[1], oa[2], oa[3]);
        da[1] = make_float4(oa[4], oa[5], oa[6], oa[7]);
        db[0] = make_float4(ob[0], ob[1], ob[2], ob[3]);
        db[1] = make_float4(ob[4], ob[5], ob[6], ob[7]);
    }
}

// ================= per-dim absmax of Wh =================
__global__ __launch_bounds__(256) void colmax_kernel(const float* __restrict__ Wh,
                                                     float* __restrict__ colmax) {
    int d = threadIdx.x;
    int r0 = blockIdx.x * 128;
    float m = 1e-30f;
    for (int r = 0; r < 128; ++r)
        m = fmaxf(m, fabsf(Wh[(size_t)(r0 + r) * DIM + d]));
    atomicMax(reinterpret_cast<unsigned int*>(&colmax[d]), __float_as_uint(m));
}

// ================= transpose + int16 quantize (k-permuted layout) =================
__global__ __launch_bounds__(256) void trans_quant_kernel(const float* __restrict__ Wh,
                                                          const float* __restrict__ colmax,
                                                          uint8_t* __restrict__ Bh8,
                                                          uint8_t* __restrict__ Bl8) {
    __shared__ float tile[64][65];
    int t = threadIdx.x;
    int n0 = blockIdx.x * 64;
    int d0 = blockIdx.y * 64;
#pragma unroll
    for (int u = 0; u < 16; ++u) {
        int idx = t + u * 256;
        int r = idx >> 6, c = idx & 63;
        tile[r][c] = Wh[(size_t)(n0 + r) * DIM + d0 + c];
    }
    __syncthreads();
#pragma unroll
    for (int u = 0; u < 4; ++u) {
        int idx = t + u * 256;          // 1024 items: 64 dims x 16 j-chunks
        int dd = idx >> 4, jg = idx & 15;
        float qb = 32000.0f / colmax[d0 + dd];
        uint32_t hp = 0, lp = 0;
#pragma unroll
        for (int v = 0; v < 4; ++v) {
            int b16 = __float2int_rn(tile[jg * 4 + v][dd] * qb);
            int bh = (b16 + 128) >> 8;
            int bl = b16 - (bh << 8);
            hp |= (uint32_t)(bh & 255) << (v * 8);
            lp |= (uint32_t)(bl & 255) << (v * 8);
        }
        // k-permuted position within the 64-node block (local chunk index jg)
        size_t off = (size_t)(d0 + dd) * NN + n0 + kperm(jg);
        *reinterpret_cast<uint32_t*>(Bh8 + off) = hp;
        *reinterpret_cast<uint32_t*>(Bl8 + off) = lp;
    }
}

// ================= s = Wh@a_src, d = Wh@a_dst =================
__global__ __launch_bounds__(256) void rowdot_kernel(const float* __restrict__ Wh,
                                                     const float* __restrict__ asrc,
                                                     const float* __restrict__ adst,
                                                     float* __restrict__ s,
                                                     float* __restrict__ d) {
    int gw = (blockIdx.x * blockDim.x + threadIdx.x) >> 5;
    int lane = threadIdx.x & 31;
    if (gw >= NN) return;
    const float* row = Wh + (size_t)gw * DIM;
    float ps = 0.0f, pd = 0.0f;
#pragma unroll
    for (int q = 0; q < 8; ++q) {
        float v = row[lane + 32 * q];
        ps = fmaf(v, asrc[lane + 32 * q], ps);
        pd = fmaf(v, adst[lane + 32 * q], pd);
    }
#pragma unroll
    for (int off = 16; off > 0; off >>= 1) {
        ps += __shfl_xor_sync(0xffffffffu, ps, off);
        pd += __shfl_xor_sync(0xffffffffu, pd, off);
    }
    if (lane == 0) { s[gw] = ps; d[gw] = pd; }
}

// ================= per-node softmax factors + row quant scale =================
__global__ __launch_bounds__(1024) void factors_kernel(const float* __restrict__ s,
                                                       const float* __restrict__ d,
                                                       float4* __restrict__ EEpG,
                                                       float2* __restrict__ FFp) {
    __shared__ float rs[1024];
    __shared__ float rd[1024];
    int t = threadIdx.x;
    float ms = -3.4e38f, md = -3.4e38f;
    for (int idx = t; idx < NN; idx += 1024) {
        ms = fmaxf(ms, s[idx]);
        md = fmaxf(md, d[idx]);
    }
    rs[t] = ms; rd[t] = md;
    __syncthreads();
    for (int off = 512; off > 0; off >>= 1) {
        if (t < off) {
            rs[t] = fmaxf(rs[t], rs[t + off]);
            rd[t] = fmaxf(rd[t], rd[t + off]);
        }
        __syncthreads();
    }
    float hh = 0.5f * (rs[0] + rd[0]);
    float Fmax = expf(rd[0] - hh);
    float Fpmax = expf(0.2f * rd[0] - hh);
    for (int idx = t; idx < NN; idx += 1024) {
        float si = s[idx], di = d[idx];
        float E = expf(si - hh), Ep = expf(0.2f * si - hh);
        float wmax = fmaxf(E * Fmax, Ep * Fpmax);
        EEpG[idx] = make_float4(E, Ep, expf(-si - hh), 32000.0f / wmax);
        FFp[idx] = make_float2(expf(di - hh), expf(0.2f * di - hh));
    }
}

// ================= int8 IMMA aggregation, KC=128, LDS.64 fragments =================
constexpr int KC = 128;
constexpr int NCH = NN / KC;   // 64
constexpr uint32_t RSTR = 160;           // row stride bytes (128 k + 32 pad)
constexpr uint32_t LIMB = 128 * RSTR;    // 20480 per limb
__device__ __forceinline__ uint32_t A_OFF(int b) { return (uint32_t)b * 40960u; }
__device__ __forceinline__ uint32_t B_OFF(int b) { return 81920u + (uint32_t)b * 40960u; }
constexpr int SM_F2 = 163840;            // float2[8192] = 64 KB
constexpr int SM_COEF = 229376;          // float[128]
constexpr int SM_ZS = 229888;            // float[128]
constexpr int GAT_SMEM = 230400;
constexpr int GAT_NT = 384;              // 8 consumer warps + 4 producer warps

__global__ __launch_bounds__(GAT_NT, 1) void gat_imma_kernel(
    const uint32_t* __restrict__ adjP,
    const uint8_t* __restrict__ Bh8, const uint8_t* __restrict__ Bl8,
    const float4* __restrict__ EEpG, const float2* __restrict__ FFp,
    const float* __restrict__ colmax, float* __restrict__ out) {
    extern __shared__ __align__(1024) char sm[];
    uint32_t sb = (uint32_t)__cvta_generic_to_shared(sm);
    int t = threadIdx.x, wid = t >> 5, lane = t & 31;
    int gid = lane >> 2, tid4 = lane & 3;
    int rb = blockIdx.x >> 1, h = blockIdx.x & 1, i0 = rb * 128;
    bool producer = (wid >= 8);
    int pt = t - 256;                 // producer row 0..127
    int rg = wid & 3, cg = wid >> 2;  // consumer tile coords (wid<8)

    // preload F/Fp pairs + this CTA's dim-half coefs into smem
    {
        const float4* src = reinterpret_cast<const float4*>(FFp);
        float4* dst = reinterpret_cast<float4*>(sm + SM_F2);
        for (int idx = t; idx < NN / 2; idx += GAT_NT) dst[idx] = src[idx];
        if (t < 128)
            reinterpret_cast<float*>(sm + SM_COEF)[t] =
                colmax[h * 128 + t] * (1.0f / 32000.0f);
    }

    // producer state
    float E = 0.0f, Ep = 0.0f, G = 0.0f, qs = 0.0f;
    int isum = 0;
    const uint32_t* wp = nullptr;
    if (producer) {
        float4 eg = EEpG[i0 + pt];
        E = eg.x; Ep = eg.y; G = eg.z; qs = eg.w;
        wp = adjP + (size_t)(i0 + pt) * (NN / 32);
    }
    const uint8_t* srcH = Bh8 + (size_t)h * 128 * NN;
    const uint8_t* srcL = Bl8 + (size_t)h * 128 * NN;

    // consumer accumulators: [mt][np][4]
    int ahh[2][8][4], amid[2][8][4];
#pragma unroll
    for (int m = 0; m < 2; ++m)
#pragma unroll
        for (int n = 0; n < 8; ++n)
#pragma unroll
            for (int j = 0; j < 4; ++j) { ahh[m][n][j] = 0; amid[m][n][j] = 0; }

    __syncthreads();   // F2/coef visible

    auto issueB = [&](int p, int buf) {
#pragma unroll
        for (int k = 0; k < 16; ++k) {
            int id = pt + 128 * k;             // 2048 16B chunks: 2 limbs x 128 dims x 8
            int limb = id >> 10;
            int rem = id & 1023;
            int d = rem >> 3, u = rem & 7;
            const uint8_t* src = (limb ? srcL : srcH) + (size_t)d * NN + p * KC + u * 16;
            cpasync16(sb + B_OFF(buf) + (uint32_t)limb * LIMB + d * RSTR + u * 16, src);
        }
        cpasync_commit();
    };
    auto buildA = [&](int p, int buf) {
        uint32_t aw[4];
#pragma unroll
        for (int q = 0; q < 4; ++q) aw[q] = wp[4 * p + q];
        const float4* f4p = reinterpret_cast<const float4*>(sm + SM_F2) + p * 64;
        char* a0 = sm + A_OFF(buf) + pt * RSTR;
#pragma unroll 4
        for (int u = 0; u < 32; ++u) {
            float4 fa = f4p[2 * u];
            float4 fb = f4p[2 * u + 1];
            uint32_t bits = aw[u >> 3] >> ((u & 7) * 4);
            float w0 = (fa.x > G) ? E * fa.x : Ep * fa.y;
            float w1 = (fa.z > G) ? E * fa.z : Ep * fa.w;
            float w2 = (fb.x > G) ? E * fb.x : Ep * fb.y;
            float w3 = (fb.z > G) ? E * fb.z : Ep * fb.w;
            w0 = (bits & 1u) ? w0 : 0.0f;
            w1 = (bits & 2u) ? w1 : 0.0f;
            w2 = (bits & 4u) ? w2 : 0.0f;
            w3 = (bits & 8u) ? w3 : 0.0f;
            int q0 = __float2int_rn(w0 * qs);
            int q1 = __float2int_rn(w1 * qs);
            int q2 = __float2int_rn(w2 * qs);
            int q3 = __float2int_rn(w3 * qs);
            isum += (q0 + q1) + (q2 + q3);
            int h0 = (q0 + 128) >> 8, h1 = (q1 + 128) >> 8;
            int h2 = (q2 + 128) >> 8, h3 = (q3 + 128) >> 8;
            uint32_t hp = (uint32_t)h0 | ((uint32_t)h1 << 8) |
                          ((uint32_t)h2 << 16) | ((uint32_t)h3 << 24);
            uint32_t lp = (uint32_t)((q0 - (h0 << 8)) & 255) |
                          ((uint32_t)((q1 - (h1 << 8)) & 255) << 8) |
                          ((uint32_t)((q2 - (h2 << 8)) & 255) << 16) |
                          ((uint32_t)((q3 - (h3 << 8)) & 255) << 24);
            int off = kperm(u);
            *reinterpret_cast<uint32_t*>(a0 + off) = hp;
            *reinterpret_cast<uint32_t*>(a0 + LIMB + off) = lp;
        }
    };

    // prologue: stage chunk 0
    if (producer) {
        issueB(0, 0);
        buildA(0, 0);
        cpasync_wait0();
    }
    __syncthreads();

    for (int p = 0; p < NCH; ++p) {
        int buf = p & 1;
        if (producer) {
            if (p + 1 < NCH) {
                issueB(p + 1, buf ^ 1);
                buildA(p + 1, buf ^ 1);
                cpasync_wait0();
            }
        } else {
            const char* aB = sm + A_OFF(buf);
            const char* bB = sm + B_OFF(buf);
#pragma unroll
            for (int kst = 0; kst < 4; ++kst) {
                uint32_t af[2][2][4];
#pragma unroll
                for (int mt = 0; mt < 2; ++mt) {
#pragma unroll
                    for (int limb = 0; limb < 2; ++limb) {
                        const char* ap = aB + limb * LIMB +
                                         (rg * 32 + mt * 16 + gid) * RSTR +
                                         kst * 32 + tid4 * 8;
                        uint2 lo = *reinterpret_cast<const uint2*>(ap);
                        uint2 hi = *reinterpret_cast<const uint2*>(ap + 8 * RSTR);
                        af[mt][limb][0] = lo.x;   // row r,   k-lo
                        af[mt][limb][1] = hi.x;   // row r+8, k-lo
                        af[mt][limb][2] = lo.y;   // row r,   k-hi
                        af[mt][limb][3] = hi.y;   // row r+8, k-hi
                    }
                }
#pragma unroll
                for (int np = 0; np < 8; ++np) {
                    const char* bp = bB + (cg * 64 + np * 8 + gid) * RSTR +
                                     kst * 32 + tid4 * 8;
                    uint2 bhv = *reinterpret_cast<const uint2*>(bp);
                    uint2 blv = *reinterpret_cast<const uint2*>(bp + LIMB);
                    uint32_t bh[2] = {bhv.x, bhv.y};
                    uint32_t bl[2] = {blv.x, blv.y};
#pragma unroll
                    for (int mt = 0; mt < 2; ++mt) {
                        imma(ahh[mt][np], af[mt][0], bh);
                        imma(amid[mt][np], af[mt][0], bl);
                        imma(amid[mt][np], af[mt][1], bh);
                    }
                }
            }
        }
        __syncthreads();   // chunk handoff
    }

    // Z: one producer thread per row (exact int sum, scale cancels)
    float* Zs = reinterpret_cast<float*>(sm + SM_ZS);
    if (producer) Zs[pt] = (float)isum;
    __syncthreads();

    // epilogue: out = elu( coef_d * (65536*hh + 256*mid) / Z_int )
    if (!producer) {
        const float* coefS = reinterpret_cast<const float*>(sm + SM_COEF);
#pragma unroll
        for (int mt = 0; mt < 2; ++mt) {
            int r0 = rg * 32 + mt * 16 + gid;
            float rz0 = 1.0f / Zs[r0];
            float rz1 = 1.0f / Zs[r0 + 8];
            float* row0 = out + (size_t)(i0 + r0) * DIM + h * 128 + cg * 64 + tid4 * 2;
            float* row1 = row0 + (size_t)8 * DIM;
#pragma unroll
            for (int np = 0; np < 8; ++np) {
                float2 cf = *reinterpret_cast<const float2*>(coefS + cg * 64 + np * 8 + tid4 * 2);
                const int* chh = ahh[mt][np];
                const int* cmd = amid[mt][np];
                float v0 = fmaf(65536.0f, (float)chh[0], 256.0f * (float)cmd[0]);
                float v1 = fmaf(65536.0f, (float)chh[1], 256.0f * (float)cmd[1]);
                float v2 = fmaf(65536.0f, (float)chh[2], 256.0f * (float)cmd[2]);
                float v3 = fmaf(65536.0f, (float)chh[3], 256.0f * (float)cmd[3]);
                float2 o0 = make_float2(elu1(v0 * cf.x * rz0), elu1(v1 * cf.y * rz0));
                float2 o1 = make_float2(elu1(v2 * cf.x * rz1), elu1(v3 * cf.y * rz1));
                *reinterpret_cast<float2*>(row0 + np * 8) = o0;
                *reinterpret_cast<float2*>(row1 + np * 8) = o1;
            }
        }
    }
}

// ================= host orchestration =================
extern "C" void kernel_launch(void* const* d_in, const int* in_sizes, int n_in,
                              void* d_out, int out_size) {
    const float* V   = (const float*)d_in[0];
    const int*   adj = (const int*)d_in[1];
    const float* W1  = (const float*)d_in[2];
    const float* as1 = (const float*)d_in[3];
    const float* ad1 = (const float*)d_in[4];
    const float* W2  = (const float*)d_in[5];
    const float* as2 = (const float*)d_in[6];
    const float* ad2 = (const float*)d_in[7];
    float* out = (float*)d_out;

    float *Wh, *H, *s, *d, *colmax;
    float4* EEpG;
    float2* FFp;
    uint8_t *Bh8, *Bl8;
    uint32_t* adjP;
    cudaGetSymbolAddress((void**)&Wh, g_Wh);
    cudaGetSymbolAddress((void**)&H, g_H);
    cudaGetSymbolAddress((void**)&s, g_s);
    cudaGetSymbolAddress((void**)&d, g_d);
    cudaGetSymbolAddress((void**)&EEpG, g_EEpG);
    cudaGetSymbolAddress((void**)&FFp, g_FFp);
    cudaGetSymbolAddress((void**)&Bh8, g_Bh8);
    cudaGetSymbolAddress((void**)&Bl8, g_Bl8);
    cudaGetSymbolAddress((void**)&colmax, g_colmax);
    cudaGetSymbolAddress((void**)&adjP, g_adjP);

    cudaFuncSetAttribute(gat_imma_kernel,
                         cudaFuncAttributeMaxDynamicSharedMemorySize, GAT_SMEM);

    pack_adj_kernel<<<8192, 256>>>(adj, adjP);

    // ---- layer 1 ----
    gemm_wh_kernel<<<NN / GW_BM, GW_NT>>>(V, W1, Wh);
    cudaMemsetAsync(colmax, 0, DIM * sizeof(float));
    colmax_kernel<<<64, 256>>>(Wh, colmax);
    trans_quant_kernel<<<dim3(128, 4), 256>>>(Wh, colmax, Bh8, Bl8);
    rowdot_kernel<<<NN * 32 / 256, 256>>>(Wh, as1, ad1, s, d);
    factors_kernel<<<1, 1024>>>(s, d, EEpG, FFp);
    gat_imma_kernel<<<128, GAT_NT, GAT_SMEM>>>(adjP, Bh8, Bl8, EEpG, FFp, colmax, H);

    // ---- layer 2 ----
    gemm_wh_kernel<<<NN / GW_BM, GW_NT>>>(H, W2, Wh);
    cudaMemsetAsync(colmax, 0, DIM * sizeof(float));
    colmax_kernel<<<64, 256>>>(Wh, colmax);
    trans_quant_kernel<<<dim3(128, 4), 256>>>(Wh, colmax, Bh8, Bl8);
    rowdot_kernel<<<NN * 32 / 256, 256>>>(Wh, as2, ad2, s, d);
    factors_kernel<<<1, 1024>>>(s, d, EEpG, FFp);
    gat_imma_kernel<<<128, GAT_NT, GAT_SMEM>>>(adjP, Bh8, Bl8, EEpG, FFp, colmax, out);
}

// round 14
// speedup vs baseline: 1.2281x; 1.2281x over previous
#include <cuda_runtime.h>
#include <cuda_bf16.h>
#include <cstdint>
#include <cstddef>

#define NN 8192
#define DIM 256

// ---------------- device-global scratch ----------------
__device__ float g_Wh[NN * DIM];
__device__ float g_H[NN * DIM];
__device__ float g_s[NN];
__device__ float g_d[NN];
__device__ float4 g_EEpG[NN];                 // (E, Ep, G, qs) per node
__device__ float2 g_FFp[NN];                  // (F, Fp) per node
__device__ uint8_t g_Bh8[DIM * NN];           // B16 high limb (s8), [dim][node]
__device__ uint8_t g_Bl8[DIM * NN];           // B16 low  limb (s8, debiased)
__device__ float g_colmax[DIM];               // per-dim absmax of Wh
__device__ uint32_t g_adjP[NN * (NN / 32)];   // bit-packed adjacency

// ---------------- helpers ----------------
__device__ __forceinline__ void cpasync16(uint32_t saddr, const void* g) {
    asm volatile("cp.async.cg.shared.global [%0], [%1], 16;" :: "r"(saddr), "l"(g));
}
__device__ __forceinline__ void cpasync_commit() { asm volatile("cp.async.commit_group;"); }
__device__ __forceinline__ void cpasync_wait0() { asm volatile("cp.async.wait_group 0;"); }
__device__ __forceinline__ float elu1(float x) { return x > 0.0f ? x : expm1f(x); }

// int8 tensor-core MMA, K=32
__device__ __forceinline__ void imma(int* c, const uint32_t* a, const uint32_t* b) {
    asm volatile(
        "mma.sync.aligned.m16n8k32.row.col.s32.s8.s8.s32 "
        "{%0,%1,%2,%3}, {%4,%5,%6,%7}, {%8,%9}, {%0,%1,%2,%3};"
        : "+r"(c[0]), "+r"(c[1]), "+r"(c[2]), "+r"(c[3])
        : "r"(a[0]), "r"(a[1]), "r"(a[2]), "r"(a[3]), "r"(b[0]), "r"(b[1]));
}

// f32x2 helpers for the feature GEMM
__device__ __forceinline__ unsigned long long pk2(float lo, float hi) {
    unsigned long long r;
    asm("mov.b64 %0, {%1, %2};" : "=l"(r) : "f"(lo), "f"(hi));
    return r;
}
__device__ __forceinline__ void upk2(unsigned long long v, float& lo, float& hi) {
    asm("mov.b64 {%0, %1}, %2;" : "=f"(lo), "=f"(hi) : "l"(v));
}
__device__ __forceinline__ void fma2(unsigned long long& acc, unsigned long long a,
                                     unsigned long long b) {
    asm("fma.rn.f32x2 %0, %1, %2, %0;" : "+l"(acc) : "l"(a), "l"(b));
}

// ================= adj bit-pack =================
__global__ __launch_bounds__(256) void pack_adj_kernel(const int* __restrict__ adj,
                                                       uint32_t* __restrict__ adjP) {
    int warpId = (blockIdx.x * 256 + threadIdx.x) >> 5;
    int lane = threadIdx.x & 31;
    const int* base = adj + (size_t)warpId * 1024;
    uint32_t w = 0;
#pragma unroll
    for (int k = 0; k < 32; ++k) {
        uint32_t b = __ballot_sync(0xffffffffu, base[k * 32 + lane] != 0);
        if (lane == k) w = b;
    }
    adjP[(size_t)warpId * 32 + lane] = w;
}

// ======= Wh = X @ W (SIMT f32x2) + FUSED rowdot (s,d) + colmax =======
constexpr int GW_BM = 64, GW_BK = 32, GW_NT = 256, GW_ASTR = 68;

__device__ __forceinline__ void mm_block(const float* As, const float* Bs,
                                         unsigned long long acc[32], int r0, int c0) {
#pragma unroll 8
    for (int kk = 0; kk < GW_BK; ++kk) {
        float4 a0 = *reinterpret_cast<const float4*>(As + kk * GW_ASTR + r0);
        float4 a1 = *reinterpret_cast<const float4*>(As + kk * GW_ASTR + r0 + 4);
        float4 b0 = *reinterpret_cast<const float4*>(Bs + kk * DIM + c0);
        float4 b1 = *reinterpret_cast<const float4*>(Bs + kk * DIM + c0 + 4);
        unsigned long long ap[4];
        ap[0] = pk2(a0.x, a0.y); ap[1] = pk2(a0.z, a0.w);
        ap[2] = pk2(a1.x, a1.y); ap[3] = pk2(a1.z, a1.w);
        float bv[8] = {b0.x, b0.y, b0.z, b0.w, b1.x, b1.y, b1.z, b1.w};
#pragma unroll
        for (int n = 0; n < 8; ++n) {
            unsigned long long bb = pk2(bv[n], bv[n]);
#pragma unroll
            for (int m = 0; m < 4; ++m) fma2(acc[m * 8 + n], ap[m], bb);
        }
    }
}

__global__ __launch_bounds__(GW_NT) void gemm_wh_kernel(const float* __restrict__ X,
                                                        const float* __restrict__ W,
                                                        const float* __restrict__ asrc,
                                                        const float* __restrict__ adst,
                                                        float* __restrict__ out,
                                                        float* __restrict__ s,
                                                        float* __restrict__ d,
                                                        float* __restrict__ colmax) {
    __shared__ float As[GW_BK * GW_ASTR];
    __shared__ float Bs[GW_BK * DIM];
    int t = threadIdx.x;
    int i0 = blockIdx.x * GW_BM;
    int tA_r = t >> 2, tA_c = t & 3;
    int tr = t >> 5, tc = t & 31;
    int r0 = tr * 8, c0 = tc * 8;
    unsigned long long acc[32];
#pragma unroll
    for (int i = 0; i < 32; ++i) acc[i] = 0ull;

    for (int p = 0; p < DIM / GW_BK; ++p) {
        int k0 = p * GW_BK;
        const float4* xsrc = reinterpret_cast<const float4*>(
            X + (size_t)(i0 + tA_r) * DIM + k0 + tA_c * 8);
        float4 x0 = xsrc[0], x1 = xsrc[1];
        __syncthreads();
        float xv[8] = {x0.x, x0.y, x0.z, x0.w, x1.x, x1.y, x1.z, x1.w};
#pragma unroll
        for (int u = 0; u < 8; ++u) As[(tA_c * 8 + u) * GW_ASTR + tA_r] = xv[u];
        const float4* wsrc = reinterpret_cast<const float4*>(W + (size_t)k0 * DIM);
        float4* bdst = reinterpret_cast<float4*>(Bs);
#pragma unroll
        for (int k = 0; k < 8; ++k) bdst[t + k * GW_NT] = wsrc[t + k * GW_NT];
        __syncthreads();
        mm_block(As, Bs, acc, r0, c0);
    }

    // load attention vectors for this thread's 8 cols
    float as8[8], ad8[8];
    {
        float4 a0 = *reinterpret_cast<const float4*>(asrc + c0);
        float4 a1 = *reinterpret_cast<const float4*>(asrc + c0 + 4);
        float4 d0 = *reinterpret_cast<const float4*>(adst + c0);
        float4 d1 = *reinterpret_cast<const float4*>(adst + c0 + 4);
        as8[0] = a0.x; as8[1] = a0.y; as8[2] = a0.z; as8[3] = a0.w;
        as8[4] = a1.x; as8[5] = a1.y; as8[6] = a1.z; as8[7] = a1.w;
        ad8[0] = d0.x; ad8[1] = d0.y; ad8[2] = d0.z; ad8[3] = d0.w;
        ad8[4] = d1.x; ad8[5] = d1.y; ad8[6] = d1.z; ad8[7] = d1.w;
    }
    float ps[8], pd[8], cmax[8];
#pragma unroll
    for (int i = 0; i < 8; ++i) { ps[i] = 0.0f; pd[i] = 0.0f; cmax[i] = 1e-30f; }

#pragma unroll
    for (int m = 0; m < 4; ++m) {
        int ra = r0 + 2 * m;
        float oa[8], ob[8];
#pragma unroll
        for (int n = 0; n < 8; ++n) upk2(acc[m * 8 + n], oa[n], ob[n]);
        float4* da = reinterpret_cast<float4*>(out + (size_t)(i0 + ra) * DIM + c0);
        float4* db = reinterpret_cast<float4*>(out + (size_t)(i0 + ra + 1) * DIM + c0);
        da[0] = make_float4(oa[0], oa[1], oa[2], oa[3]);
        da[1] = make_float4(oa[4], oa[5], oa[6], oa[7]);
        db[0] = make_float4(ob[0], ob[1], ob[2], ob[3]);
        db[1] = make_float4(ob[4], ob[5], ob[6], ob[7]);
#pragma unroll
        for (int n = 0; n < 8; ++n) {
            ps[2 * m]     = fmaf(oa[n], as8[n], ps[2 * m]);
            pd[2 * m]     = fmaf(oa[n], ad8[n], pd[2 * m]);
            ps[2 * m + 1] = fmaf(ob[n], as8[n], ps[2 * m + 1]);
            pd[2 * m + 1] = fmaf(ob[n], ad8[n], pd[2 * m + 1]);
            cmax[n] = fmaxf(cmax[n], fmaxf(fabsf(oa[n]), fabsf(ob[n])));
        }
    }

    // rowdot: warp tr owns rows r0..r0+7 fully (lanes = 32 col-groups) -> shfl reduce
#pragma unroll
    for (int off = 16; off > 0; off >>= 1) {
#pragma unroll
        for (int r = 0; r < 8; ++r) {
            ps[r] += __shfl_xor_sync(0xffffffffu, ps[r], off);
            pd[r] += __shfl_xor_sync(0xffffffffu, pd[r], off);
        }
    }
    if (tc == 0) {
#pragma unroll
        for (int r = 0; r < 8; ++r) {
            s[i0 + r0 + r] = ps[r];
            d[i0 + r0 + r] = pd[r];
        }
    }

    // colmax: reduce 8 warps' per-col maxima in smem (reuse Bs), then atomicMax
    __syncthreads();   // all mm_block reads of Bs done
    float* cm = Bs;    // [8 warps][256 cols]
#pragma unroll
    for (int n = 0; n < 8; ++n) cm[tr * DIM + c0 + n] = cmax[n];
    __syncthreads();
    if (t < DIM) {
        float m = cm[t];
#pragma unroll
        for (int w = 1; w < 8; ++w) m = fmaxf(m, cm[w * DIM + t]);
        atomicMax(reinterpret_cast<unsigned int*>(&colmax[t]), __float_as_uint(m));
    }
}

// ================= transpose + int16 fixed-point quantize =================
__global__ __launch_bounds__(256) void trans_quant_kernel(const float* __restrict__ Wh,
                                                          const float* __restrict__ colmax,
                                                          uint8_t* __restrict__ Bh8,
                                                          uint8_t* __restrict__ Bl8) {
    __shared__ float tile[64][65];
    int t = threadIdx.x;
    int n0 = blockIdx.x * 64;
    int d0 = blockIdx.y * 64;
#pragma unroll
    for (int u = 0; u < 16; ++u) {
        int idx = t + u * 256;
        int r = idx >> 6, c = idx & 63;
        tile[r][c] = Wh[(size_t)(n0 + r) * DIM + d0 + c];
    }
    __syncthreads();
#pragma unroll
    for (int u = 0; u < 4; ++u) {
        int idx = t + u * 256;
        int dd = idx >> 4, jg = idx & 15;
        float qb = 32000.0f / colmax[d0 + dd];
        uint32_t hp = 0, lp = 0;
#pragma unroll
        for (int v = 0; v < 4; ++v) {
            int b16 = __float2int_rn(tile[jg * 4 + v][dd] * qb);
            int bh = (b16 + 128) >> 8;
            int bl = b16 - (bh << 8);
            hp |= (uint32_t)(bh & 255) << (v * 8);
            lp |= (uint32_t)(bl & 255) << (v * 8);
        }
        size_t off = (size_t)(d0 + dd) * NN + n0 + jg * 4;
        *reinterpret_cast<uint32_t*>(Bh8 + off) = hp;
        *reinterpret_cast<uint32_t*>(Bl8 + off) = lp;
    }
}

// ================= per-node softmax factors + row quant scale =================
__global__ __launch_bounds__(1024) void factors_kernel(const float* __restrict__ s,
                                                       const float* __restrict__ d,
                                                       float4* __restrict__ EEpG,
                                                       float2* __restrict__ FFp) {
    __shared__ float rs[1024];
    __shared__ float rd[1024];
    int t = threadIdx.x;
    float ms = -3.4e38f, md = -3.4e38f;
    for (int idx = t; idx < NN; idx += 1024) {
        ms = fmaxf(ms, s[idx]);
        md = fmaxf(md, d[idx]);
    }
    rs[t] = ms; rd[t] = md;
    __syncthreads();
    for (int off = 512; off > 0; off >>= 1) {
        if (t < off) {
            rs[t] = fmaxf(rs[t], rs[t + off]);
            rd[t] = fmaxf(rd[t], rd[t + off]);
        }
        __syncthreads();
    }
    float hh = 0.5f * (rs[0] + rd[0]);
    float Fmax = expf(rd[0] - hh);
    float Fpmax = expf(0.2f * rd[0] - hh);
    for (int idx = t; idx < NN; idx += 1024) {
        float si = s[idx], di = d[idx];
        float E = expf(si - hh), Ep = expf(0.2f * si - hh);
        float wmax = fmaxf(E * Fmax, Ep * Fpmax);
        EEpG[idx] = make_float4(E, Ep, expf(-si - hh), 32000.0f / wmax);
        FFp[idx] = make_float2(expf(di - hh), expf(0.2f * di - hh));
    }
}

// ================= int8 IMMA aggregation (round-11 exact) =================
constexpr int KC = 64;
constexpr int NCH = NN / KC;   // 128
__device__ __forceinline__ uint32_t A_OFF(int b) { return (uint32_t)b * 20480u; }
constexpr uint32_t ALIMB = 10240;
__device__ __forceinline__ uint32_t B_OFF(int b) { return 40960u + (uint32_t)b * 36864u; }
constexpr uint32_t BLIMB = 18432;
constexpr int SM_F2 = 114688;          // float2[8192] = 64 KB
constexpr int SM_COEF = 180224;        // float[128]
constexpr int SM_ZS = 181248;          // float[128]
constexpr int GAT_SMEM = 181760;
constexpr int GAT_NT = 384;

__global__ __launch_bounds__(GAT_NT, 1) void gat_imma_kernel(
    const uint32_t* __restrict__ adjP,
    const uint8_t* __restrict__ Bh8, const uint8_t* __restrict__ Bl8,
    const float4* __restrict__ EEpG, const float2* __restrict__ FFp,
    const float* __restrict__ colmax, float* __restrict__ out) {
    extern __shared__ __align__(1024) char sm[];
    uint32_t sb = (uint32_t)__cvta_generic_to_shared(sm);
    int t = threadIdx.x, wid = t >> 5, lane = t & 31;
    int gid = lane >> 2, tid4 = lane & 3;
    int rb = blockIdx.x >> 1, h = blockIdx.x & 1, i0 = rb * 128;
    bool producer = (wid >= 8);
    int pt = t - 256;
    int rg = wid & 3, cg = wid >> 2;

    {
        const float4* src = reinterpret_cast<const float4*>(FFp);
        float4* dst = reinterpret_cast<float4*>(sm + SM_F2);
        for (int idx = t; idx < NN / 2; idx += GAT_NT) dst[idx] = src[idx];
        if (t < 128)
            reinterpret_cast<float*>(sm + SM_COEF)[t] =
                colmax[h * 128 + t] * (1.0f / 32000.0f);
    }

    float E = 0.0f, Ep = 0.0f, G = 0.0f, qs = 0.0f;
    int isum = 0;
    const uint32_t* wp = nullptr;
    if (producer) {
        float4 eg = EEpG[i0 + pt];
        E = eg.x; Ep = eg.y; G = eg.z; qs = eg.w;
        wp = adjP + (size_t)(i0 + pt) * (NN / 32);
    }
    const uint8_t* srcH = Bh8 + (size_t)h * 128 * NN;
    const uint8_t* srcL = Bl8 + (size_t)h * 128 * NN;

    int ahh[2][8][4], amid[2][8][4];
#pragma unroll
    for (int m = 0; m < 2; ++m)
#pragma unroll
        for (int n = 0; n < 8; ++n)
#pragma unroll
            for (int j = 0; j < 4; ++j) { ahh[m][n][j] = 0; amid[m][n][j] = 0; }

    __syncthreads();

    auto issueB = [&](int p, int buf) {
#pragma unroll
        for (int k = 0; k < 8; ++k) {
            int id = pt + 128 * k;
            int limb = id >> 9;
            int rem = id & 511;
            int d = rem >> 2, u = rem & 3;
            const uint8_t* src = (limb ? srcL : srcH) + (size_t)d * NN + p * 64 + u * 16;
            cpasync16(sb + B_OFF(buf) + (uint32_t)limb * BLIMB + d * 144 + u * 16, src);
        }
        cpasync_commit();
    };
    auto buildA = [&](int p, int buf) {
        uint32_t aw0 = wp[2 * p], aw1 = wp[2 * p + 1];
        const float4* f4p = reinterpret_cast<const float4*>(sm + SM_F2) + p * 32;
        char* a0 = sm + A_OFF(buf) + pt * 80;
#pragma unroll 4
        for (int u = 0; u < 16; ++u) {
            float4 fa = f4p[2 * u];
            float4 fb = f4p[2 * u + 1];
            uint32_t bits = ((u < 8) ? aw0 : aw1) >> ((u & 7) * 4);
            float w0 = (fa.x > G) ? E * fa.x : Ep * fa.y;
            float w1 = (fa.z > G) ? E * fa.z : Ep * fa.w;
            float w2 = (fb.x > G) ? E * fb.x : Ep * fb.y;
            float w3 = (fb.z > G) ? E * fb.z : Ep * fb.w;
            w0 = (bits & 1u) ? w0 : 0.0f;
            w1 = (bits & 2u) ? w1 : 0.0f;
            w2 = (bits & 4u) ? w2 : 0.0f;
            w3 = (bits & 8u) ? w3 : 0.0f;
            int q0 = __float2int_rn(w0 * qs);
            int q1 = __float2int_rn(w1 * qs);
            int q2 = __float2int_rn(w2 * qs);
            int q3 = __float2int_rn(w3 * qs);
            isum += (q0 + q1) + (q2 + q3);
            int h0 = (q0 + 128) >> 8, h1 = (q1 + 128) >> 8;
            int h2 = (q2 + 128) >> 8, h3 = (q3 + 128) >> 8;
            uint32_t hp = (uint32_t)h0 | ((uint32_t)h1 << 8) |
                          ((uint32_t)h2 << 16) | ((uint32_t)h3 << 24);
            uint32_t lp = (uint32_t)((q0 - (h0 << 8)) & 255) |
                          ((uint32_t)((q1 - (h1 << 8)) & 255) << 8) |
                          ((uint32_t)((q2 - (h2 << 8)) & 255) << 16) |
                          ((uint32_t)((q3 - (h3 << 8)) & 255) << 24);
            *reinterpret_cast<uint32_t*>(a0 + u * 4) = hp;
            *reinterpret_cast<uint32_t*>(a0 + ALIMB + u * 4) = lp;
        }
    };

    if (producer) {
        issueB(0, 0);
        buildA(0, 0);
        cpasync_wait0();
    }
    __syncthreads();

    for (int p = 0; p < NCH; ++p) {
        int buf = p & 1;
        if (producer) {
            if (p + 1 < NCH) {
                issueB(p + 1, buf ^ 1);
                buildA(p + 1, buf ^ 1);
                cpasync_wait0();
            }
        } else {
            const char* aB = sm + A_OFF(buf);
            const char* bB = sm + B_OFF(buf);
#pragma unroll
            for (int kst = 0; kst < 2; ++kst) {
                uint32_t af[2][2][4];
#pragma unroll
                for (int mt = 0; mt < 2; ++mt) {
#pragma unroll
                    for (int limb = 0; limb < 2; ++limb) {
                        const char* ap = aB + limb * ALIMB +
                                         (rg * 32 + mt * 16 + gid) * 80 + kst * 32 + tid4 * 4;
                        af[mt][limb][0] = *reinterpret_cast<const uint32_t*>(ap);
                        af[mt][limb][1] = *reinterpret_cast<const uint32_t*>(ap + 640);
                        af[mt][limb][2] = *reinterpret_cast<const uint32_t*>(ap + 16);
                        af[mt][limb][3] = *reinterpret_cast<const uint32_t*>(ap + 656);
                    }
                }
#pragma unroll
                for (int np = 0; np < 8; ++np) {
                    const char* bp = bB + (cg * 64 + np * 8 + gid) * 144 + kst * 32 + tid4 * 4;
                    uint32_t bh[2], bl[2];
                    bh[0] = *reinterpret_cast<const uint32_t*>(bp);
                    bh[1] = *reinterpret_cast<const uint32_t*>(bp + 16);
                    bl[0] = *reinterpret_cast<const uint32_t*>(bp + BLIMB);
                    bl[1] = *reinterpret_cast<const uint32_t*>(bp + BLIMB + 16);
#pragma unroll
                    for (int mt = 0; mt < 2; ++mt) {
                        imma(ahh[mt][np], af[mt][0], bh);
                        imma(amid[mt][np], af[mt][0], bl);
                        imma(amid[mt][np], af[mt][1], bh);
                    }
                }
            }
        }
        __syncthreads();
    }

    float* Zs = reinterpret_cast<float*>(sm + SM_ZS);
    if (producer) Zs[pt] = (float)isum;
    __syncthreads();

    if (!producer) {
        const float* coefS = reinterpret_cast<const float*>(sm + SM_COEF);
#pragma unroll
        for (int mt = 0; mt < 2; ++mt) {
            int r0 = rg * 32 + mt * 16 + gid;
            float rz0 = 1.0f / Zs[r0];
            float rz1 = 1.0f / Zs[r0 + 8];
            float* row0 = out + (size_t)(i0 + r0) * DIM + h * 128 + cg * 64 + tid4 * 2;
            float* row1 = row0 + (size_t)8 * DIM;
#pragma unroll
            for (int np = 0; np < 8; ++np) {
                float2 cf = *reinterpret_cast<const float2*>(coefS + cg * 64 + np * 8 + tid4 * 2);
                const int* chh = ahh[mt][np];
                const int* cmd = amid[mt][np];
                float v0 = fmaf(65536.0f, (float)chh[0], 256.0f * (float)cmd[0]);
                float v1 = fmaf(65536.0f, (float)chh[1], 256.0f * (float)cmd[1]);
                float v2 = fmaf(65536.0f, (float)chh[2], 256.0f * (float)cmd[2]);
                float v3 = fmaf(65536.0f, (float)chh[3], 256.0f * (float)cmd[3]);
                float2 o0 = make_float2(elu1(v0 * cf.x * rz0), elu1(v1 * cf.y * rz0));
                float2 o1 = make_float2(elu1(v2 * cf.x * rz1), elu1(v3 * cf.y * rz1));
                *reinterpret_cast<float2*>(row0 + np * 8) = o0;
                *reinterpret_cast<float2*>(row1 + np * 8) = o1;
            }
        }
    }
}

// ================= host orchestration =================
extern "C" void kernel_launch(void* const* d_in, const int* in_sizes, int n_in,
                              void* d_out, int out_size) {
    const float* V   = (const float*)d_in[0];
    const int*   adj = (const int*)d_in[1];
    const float* W1  = (const float*)d_in[2];
    const float* as1 = (const float*)d_in[3];
    const float* ad1 = (const float*)d_in[4];
    const float* W2  = (const float*)d_in[5];
    const float* as2 = (const float*)d_in[6];
    const float* ad2 = (const float*)d_in[7];
    float* out = (float*)d_out;

    float *Wh, *H, *s, *d, *colmax;
    float4* EEpG;
    float2* FFp;
    uint8_t *Bh8, *Bl8;
    uint32_t* adjP;
    cudaGetSymbolAddress((void**)&Wh, g_Wh);
    cudaGetSymbolAddress((void**)&H, g_H);
    cudaGetSymbolAddress((void**)&s, g_s);
    cudaGetSymbolAddress((void**)&d, g_d);
    cudaGetSymbolAddress((void**)&EEpG, g_EEpG);
    cudaGetSymbolAddress((void**)&FFp, g_FFp);
    cudaGetSymbolAddress((void**)&Bh8, g_Bh8);
    cudaGetSymbolAddress((void**)&Bl8, g_Bl8);
    cudaGetSymbolAddress((void**)&colmax, g_colmax);
    cudaGetSymbolAddress((void**)&adjP, g_adjP);

    cudaFuncSetAttribute(gat_imma_kernel,
                         cudaFuncAttributeMaxDynamicSharedMemorySize, GAT_SMEM);

    pack_adj_kernel<<<8192, 256>>>(adj, adjP);

    // ---- layer 1 ----
    cudaMemsetAsync(colmax, 0, DIM * sizeof(float));
    gemm_wh_kernel<<<NN / GW_BM, GW_NT>>>(V, W1, as1, ad1, Wh, s, d, colmax);
    trans_quant_kernel<<<dim3(128, 4), 256>>>(Wh, colmax, Bh8, Bl8);
    factors_kernel<<<1, 1024>>>(s, d, EEpG, FFp);
    gat_imma_kernel<<<128, GAT_NT, GAT_SMEM>>>(adjP, Bh8, Bl8, EEpG, FFp, colmax, H);

    // ---- layer 2 ----
    cudaMemsetAsync(colmax, 0, DIM * sizeof(float));
    gemm_wh_kernel<<<NN / GW_BM, GW_NT>>>(H, W2, as2, ad2, Wh, s, d, colmax);
    trans_quant_kernel<<<dim3(128, 4), 256>>>(Wh, colmax, Bh8, Bl8);
    factors_kernel<<<1, 1024>>>(s, d, EEpG, FFp);
    gat_imma_kernel<<<128, GAT_NT, GAT_SMEM>>>(adjP, Bh8, Bl8, EEpG, FFp, colmax, out);
}

// round 15
// speedup vs baseline: 1.2505x; 1.0182x over previous
#include <cuda_runtime.h>
#include <cuda_bf16.h>
#include <cstdint>
#include <cstddef>

#define NN 8192
#define DIM 256

// ---------------- device-global scratch ----------------
__device__ float g_Wh[NN * DIM];
__device__ float g_H[NN * DIM];
__device__ float g_s[NN];
__device__ float g_d[NN];
__device__ float4 g_EEpG[NN];                 // (E, Ep, G, qs) per node
__device__ float2 g_FFp[NN];                  // (F, Fp) per node
__device__ uint8_t g_Bh8[DIM * NN];           // B16 high limb (s8), [dim][node]
__device__ uint8_t g_Bl8[DIM * NN];           // B16 low  limb (s8, debiased)
__device__ float g_colmax[DIM + 2];           // [0..255] per-dim absmax; [256]=smax key, [257]=dmax key
__device__ uint32_t g_adjP[NN * (NN / 32)];   // bit-packed adjacency

// ---------------- helpers ----------------
__device__ __forceinline__ void cpasync16(uint32_t saddr, const void* g) {
    asm volatile("cp.async.cg.shared.global [%0], [%1], 16;" :: "r"(saddr), "l"(g));
}
__device__ __forceinline__ void cpasync_commit() { asm volatile("cp.async.commit_group;"); }
__device__ __forceinline__ void cpasync_wait0() { asm volatile("cp.async.wait_group 0;"); }
__device__ __forceinline__ float elu1(float x) { return x > 0.0f ? x : expm1f(x); }

// ordered-uint encoding for float atomicMax (monotone, handles negatives)
__device__ __forceinline__ uint32_t fenc(float x) {
    uint32_t u = __float_as_uint(x);
    return (u & 0x80000000u) ? ~u : (u | 0x80000000u);
}
__device__ __forceinline__ float fdec(uint32_t k) {
    uint32_t u = (k & 0x80000000u) ? (k ^ 0x80000000u) : ~k;
    return __uint_as_float(u);
}

// int8 tensor-core MMA, K=32
__device__ __forceinline__ void imma(int* c, const uint32_t* a, const uint32_t* b) {
    asm volatile(
        "mma.sync.aligned.m16n8k32.row.col.s32.s8.s8.s32 "
        "{%0,%1,%2,%3}, {%4,%5,%6,%7}, {%8,%9}, {%0,%1,%2,%3};"
        : "+r"(c[0]), "+r"(c[1]), "+r"(c[2]), "+r"(c[3])
        : "r"(a[0]), "r"(a[1]), "r"(a[2]), "r"(a[3]), "r"(b[0]), "r"(b[1]));
}

// f32x2 helpers for the feature GEMM
__device__ __forceinline__ unsigned long long pk2(float lo, float hi) {
    unsigned long long r;
    asm("mov.b64 %0, {%1, %2};" : "=l"(r) : "f"(lo), "f"(hi));
    return r;
}
__device__ __forceinline__ void upk2(unsigned long long v, float& lo, float& hi) {
    asm("mov.b64 {%0, %1}, %2;" : "=f"(lo), "=f"(hi) : "l"(v));
}
__device__ __forceinline__ void fma2(unsigned long long& acc, unsigned long long a,
                                     unsigned long long b) {
    asm("fma.rn.f32x2 %0, %1, %2, %0;" : "+l"(acc) : "l"(a), "l"(b));
}

// ================= adj bit-pack =================
__global__ __launch_bounds__(256) void pack_adj_kernel(const int* __restrict__ adj,
                                                       uint32_t* __restrict__ adjP) {
    int warpId = (blockIdx.x * 256 + threadIdx.x) >> 5;
    int lane = threadIdx.x & 31;
    const int* base = adj + (size_t)warpId * 1024;
    uint32_t w = 0;
#pragma unroll
    for (int k = 0; k < 32; ++k) {
        uint32_t b = __ballot_sync(0xffffffffu, base[k * 32 + lane] != 0);
        if (lane == k) w = b;
    }
    adjP[(size_t)warpId * 32 + lane] = w;
}

// ======= Wh = X @ W (SIMT f32x2) + FUSED rowdot + colmax + s/d max =======
constexpr int GW_BM = 64, GW_BK = 32, GW_NT = 256, GW_ASTR = 68;

__device__ __forceinline__ void mm_block(const float* As, const float* Bs,
                                         unsigned long long acc[32], int r0, int c0) {
#pragma unroll 8
    for (int kk = 0; kk < GW_BK; ++kk) {
        float4 a0 = *reinterpret_cast<const float4*>(As + kk * GW_ASTR + r0);
        float4 a1 = *reinterpret_cast<const float4*>(As + kk * GW_ASTR + r0 + 4);
        float4 b0 = *reinterpret_cast<const float4*>(Bs + kk * DIM + c0);
        float4 b1 = *reinterpret_cast<const float4*>(Bs + kk * DIM + c0 + 4);
        unsigned long long ap[4];
        ap[0] = pk2(a0.x, a0.y); ap[1] = pk2(a0.z, a0.w);
        ap[2] = pk2(a1.x, a1.y); ap[3] = pk2(a1.z, a1.w);
        float bv[8] = {b0.x, b0.y, b0.z, b0.w, b1.x, b1.y, b1.z, b1.w};
#pragma unroll
        for (int n = 0; n < 8; ++n) {
            unsigned long long bb = pk2(bv[n], bv[n]);
#pragma unroll
            for (int m = 0; m < 4; ++m) fma2(acc[m * 8 + n], ap[m], bb);
        }
    }
}

__global__ __launch_bounds__(GW_NT) void gemm_wh_kernel(const float* __restrict__ X,
                                                        const float* __restrict__ W,
                                                        const float* __restrict__ asrc,
                                                        const float* __restrict__ adst,
                                                        float* __restrict__ out,
                                                        float* __restrict__ s,
                                                        float* __restrict__ d,
                                                        float* __restrict__ colmax) {
    __shared__ float As[GW_BK * GW_ASTR];
    __shared__ float Bs[GW_BK * DIM];
    int t = threadIdx.x;
    int i0 = blockIdx.x * GW_BM;
    int tA_r = t >> 2, tA_c = t & 3;
    int tr = t >> 5, tc = t & 31;
    int r0 = tr * 8, c0 = tc * 8;
    unsigned long long acc[32];
#pragma unroll
    for (int i = 0; i < 32; ++i) acc[i] = 0ull;

    for (int p = 0; p < DIM / GW_BK; ++p) {
        int k0 = p * GW_BK;
        const float4* xsrc = reinterpret_cast<const float4*>(
            X + (size_t)(i0 + tA_r) * DIM + k0 + tA_c * 8);
        float4 x0 = xsrc[0], x1 = xsrc[1];
        __syncthreads();
        float xv[8] = {x0.x, x0.y, x0.z, x0.w, x1.x, x1.y, x1.z, x1.w};
#pragma unroll
        for (int u = 0; u < 8; ++u) As[(tA_c * 8 + u) * GW_ASTR + tA_r] = xv[u];
        const float4* wsrc = reinterpret_cast<const float4*>(W + (size_t)k0 * DIM);
        float4* bdst = reinterpret_cast<float4*>(Bs);
#pragma unroll
        for (int k = 0; k < 8; ++k) bdst[t + k * GW_NT] = wsrc[t + k * GW_NT];
        __syncthreads();
        mm_block(As, Bs, acc, r0, c0);
    }

    // load attention vectors for this thread's 8 cols
    float as8[8], ad8[8];
    {
        float4 a0 = *reinterpret_cast<const float4*>(asrc + c0);
        float4 a1 = *reinterpret_cast<const float4*>(asrc + c0 + 4);
        float4 d0 = *reinterpret_cast<const float4*>(adst + c0);
        float4 d1 = *reinterpret_cast<const float4*>(adst + c0 + 4);
        as8[0] = a0.x; as8[1] = a0.y; as8[2] = a0.z; as8[3] = a0.w;
        as8[4] = a1.x; as8[5] = a1.y; as8[6] = a1.z; as8[7] = a1.w;
        ad8[0] = d0.x; ad8[1] = d0.y; ad8[2] = d0.z; ad8[3] = d0.w;
        ad8[4] = d1.x; ad8[5] = d1.y; ad8[6] = d1.z; ad8[7] = d1.w;
    }
    float ps[8], pd[8], cmax[8];
#pragma unroll
    for (int i = 0; i < 8; ++i) { ps[i] = 0.0f; pd[i] = 0.0f; cmax[i] = 1e-30f; }

#pragma unroll
    for (int m = 0; m < 4; ++m) {
        int ra = r0 + 2 * m;
        float oa[8], ob[8];
#pragma unroll
        for (int n = 0; n < 8; ++n) upk2(acc[m * 8 + n], oa[n], ob[n]);
        float4* da = reinterpret_cast<float4*>(out + (size_t)(i0 + ra) * DIM + c0);
        float4* db = reinterpret_cast<float4*>(out + (size_t)(i0 + ra + 1) * DIM + c0);
        da[0] = make_float4(oa[0], oa[1], oa[2], oa[3]);
        da[1] = make_float4(oa[4], oa[5], oa[6], oa[7]);
        db[0] = make_float4(ob[0], ob[1], ob[2], ob[3]);
        db[1] = make_float4(ob[4], ob[5], ob[6], ob[7]);
#pragma unroll
        for (int n = 0; n < 8; ++n) {
            ps[2 * m]     = fmaf(oa[n], as8[n], ps[2 * m]);
            pd[2 * m]     = fmaf(oa[n], ad8[n], pd[2 * m]);
            ps[2 * m + 1] = fmaf(ob[n], as8[n], ps[2 * m + 1]);
            pd[2 * m + 1] = fmaf(ob[n], ad8[n], pd[2 * m + 1]);
            cmax[n] = fmaxf(cmax[n], fmaxf(fabsf(oa[n]), fabsf(ob[n])));
        }
    }

    // rowdot: warp tr owns rows r0..r0+7 fully -> shfl reduce
#pragma unroll
    for (int off = 16; off > 0; off >>= 1) {
#pragma unroll
        for (int r = 0; r < 8; ++r) {
            ps[r] += __shfl_xor_sync(0xffffffffu, ps[r], off);
            pd[r] += __shfl_xor_sync(0xffffffffu, pd[r], off);
        }
    }
    if (tc == 0) {
        float ms = ps[0], md = pd[0];
#pragma unroll
        for (int r = 0; r < 8; ++r) {
            s[i0 + r0 + r] = ps[r];
            d[i0 + r0 + r] = pd[r];
            ms = fmaxf(ms, ps[r]);
            md = fmaxf(md, pd[r]);
        }
        atomicMax(reinterpret_cast<unsigned int*>(&colmax[DIM]), fenc(ms));
        atomicMax(reinterpret_cast<unsigned int*>(&colmax[DIM + 1]), fenc(md));
    }

    // colmax: reduce 8 warps' per-col maxima in smem (reuse Bs), then atomicMax
    __syncthreads();   // all mm_block reads of Bs done
    float* cm = Bs;    // [8 warps][256 cols]
#pragma unroll
    for (int n = 0; n < 8; ++n) cm[tr * DIM + c0 + n] = cmax[n];
    __syncthreads();
    if (t < DIM) {
        float m = cm[t];
#pragma unroll
        for (int w = 1; w < 8; ++w) m = fmaxf(m, cm[w * DIM + t]);
        atomicMax(reinterpret_cast<unsigned int*>(&colmax[t]), __float_as_uint(m));
    }
}

// ================= transpose + int16 fixed-point quantize =================
__global__ __launch_bounds__(256) void trans_quant_kernel(const float* __restrict__ Wh,
                                                          const float* __restrict__ colmax,
                                                          uint8_t* __restrict__ Bh8,
                                                          uint8_t* __restrict__ Bl8) {
    __shared__ float tile[64][65];
    int t = threadIdx.x;
    int n0 = blockIdx.x * 64;
    int d0 = blockIdx.y * 64;
#pragma unroll
    for (int u = 0; u < 16; ++u) {
        int idx = t + u * 256;
        int r = idx >> 6, c = idx & 63;
        tile[r][c] = Wh[(size_t)(n0 + r) * DIM + d0 + c];
    }
    __syncthreads();
#pragma unroll
    for (int u = 0; u < 4; ++u) {
        int idx = t + u * 256;
        int dd = idx >> 4, jg = idx & 15;
        float qb = 32000.0f / colmax[d0 + dd];
        uint32_t hp = 0, lp = 0;
#pragma unroll
        for (int v = 0; v < 4; ++v) {
            int b16 = __float2int_rn(tile[jg * 4 + v][dd] * qb);
            int bh = (b16 + 128) >> 8;
            int bl = b16 - (bh << 8);
            hp |= (uint32_t)(bh & 255) << (v * 8);
            lp |= (uint32_t)(bl & 255) << (v * 8);
        }
        size_t off = (size_t)(d0 + dd) * NN + n0 + jg * 4;
        *reinterpret_cast<uint32_t*>(Bh8 + off) = hp;
        *reinterpret_cast<uint32_t*>(Bl8 + off) = lp;
    }
}

// ======= per-node softmax factors (grid-parallel; maxes precomputed) =======
__global__ __launch_bounds__(256) void factors_kernel(const float* __restrict__ s,
                                                      const float* __restrict__ d,
                                                      const float* __restrict__ colmax,
                                                      float4* __restrict__ EEpG,
                                                      float2* __restrict__ FFp) {
    int idx = blockIdx.x * 256 + threadIdx.x;
    float smax = fdec(__float_as_uint(colmax[DIM]));
    float dmax = fdec(__float_as_uint(colmax[DIM + 1]));
    float hh = 0.5f * (smax + dmax);
    float Fmax = expf(dmax - hh);
    float Fpmax = expf(0.2f * dmax - hh);
    float si = s[idx], di = d[idx];
    float E = expf(si - hh), Ep = expf(0.2f * si - hh);
    float wmax = fmaxf(E * Fmax, Ep * Fpmax);
    EEpG[idx] = make_float4(E, Ep, expf(-si - hh), 32000.0f / wmax);
    FFp[idx] = make_float2(expf(di - hh), expf(0.2f * di - hh));
}

// ================= int8 IMMA aggregation (round-11 exact) =================
constexpr int KC = 64;
constexpr int NCH = NN / KC;   // 128
__device__ __forceinline__ uint32_t A_OFF(int b) { return (uint32_t)b * 20480u; }
constexpr uint32_t ALIMB = 10240;
__device__ __forceinline__ uint32_t B_OFF(int b) { return 40960u + (uint32_t)b * 36864u; }
constexpr uint32_t BLIMB = 18432;
constexpr int SM_F2 = 114688;          // float2[8192] = 64 KB
constexpr int SM_COEF = 180224;        // float[128]
constexpr int SM_ZS = 181248;          // float[128]
constexpr int GAT_SMEM = 181760;
constexpr int GAT_NT = 384;

__global__ __launch_bounds__(GAT_NT, 1) void gat_imma_kernel(
    const uint32_t* __restrict__ adjP,
    const uint8_t* __restrict__ Bh8, const uint8_t* __restrict__ Bl8,
    const float4* __restrict__ EEpG, const float2* __restrict__ FFp,
    const float* __restrict__ colmax, float* __restrict__ out) {
    extern __shared__ __align__(1024) char sm[];
    uint32_t sb = (uint32_t)__cvta_generic_to_shared(sm);
    int t = threadIdx.x, wid = t >> 5, lane = t & 31;
    int gid = lane >> 2, tid4 = lane & 3;
    int rb = blockIdx.x >> 1, h = blockIdx.x & 1, i0 = rb * 128;
    bool producer = (wid >= 8);
    int pt = t - 256;
    int rg = wid & 3, cg = wid >> 2;

    {
        const float4* src = reinterpret_cast<const float4*>(FFp);
        float4* dst = reinterpret_cast<float4*>(sm + SM_F2);
        for (int idx = t; idx < NN / 2; idx += GAT_NT) dst[idx] = src[idx];
        if (t < 128)
            reinterpret_cast<float*>(sm + SM_COEF)[t] =
                colmax[h * 128 + t] * (1.0f / 32000.0f);
    }

    float E = 0.0f, Ep = 0.0f, G = 0.0f, qs = 0.0f;
    int isum = 0;
    const uint32_t* wp = nullptr;
    if (producer) {
        float4 eg = EEpG[i0 + pt];
        E = eg.x; Ep = eg.y; G = eg.z; qs = eg.w;
        wp = adjP + (size_t)(i0 + pt) * (NN / 32);
    }
    const uint8_t* srcH = Bh8 + (size_t)h * 128 * NN;
    const uint8_t* srcL = Bl8 + (size_t)h * 128 * NN;

    int ahh[2][8][4], amid[2][8][4];
#pragma unroll
    for (int m = 0; m < 2; ++m)
#pragma unroll
        for (int n = 0; n < 8; ++n)
#pragma unroll
            for (int j = 0; j < 4; ++j) { ahh[m][n][j] = 0; amid[m][n][j] = 0; }

    __syncthreads();

    auto issueB = [&](int p, int buf) {
#pragma unroll
        for (int k = 0; k < 8; ++k) {
            int id = pt + 128 * k;
            int limb = id >> 9;
            int rem = id & 511;
            int d = rem >> 2, u = rem & 3;
            const uint8_t* src = (limb ? srcL : srcH) + (size_t)d * NN + p * 64 + u * 16;
            cpasync16(sb + B_OFF(buf) + (uint32_t)limb * BLIMB + d * 144 + u * 16, src);
        }
        cpasync_commit();
    };
    auto buildA = [&](int p, int buf) {
        uint32_t aw0 = wp[2 * p], aw1 = wp[2 * p + 1];
        const float4* f4p = reinterpret_cast<const float4*>(sm + SM_F2) + p * 32;
        char* a0 = sm + A_OFF(buf) + pt * 80;
#pragma unroll 4
        for (int u = 0; u < 16; ++u) {
            float4 fa = f4p[2 * u];
            float4 fb = f4p[2 * u + 1];
            uint32_t bits = ((u < 8) ? aw0 : aw1) >> ((u & 7) * 4);
            float w0 = (fa.x > G) ? E * fa.x : Ep * fa.y;
            float w1 = (fa.z > G) ? E * fa.z : Ep * fa.w;
            float w2 = (fb.x > G) ? E * fb.x : Ep * fb.y;
            float w3 = (fb.z > G) ? E * fb.z : Ep * fb.w;
            w0 = (bits & 1u) ? w0 : 0.0f;
            w1 = (bits & 2u) ? w1 : 0.0f;
            w2 = (bits & 4u) ? w2 : 0.0f;
            w3 = (bits & 8u) ? w3 : 0.0f;
            int q0 = __float2int_rn(w0 * qs);
            int q1 = __float2int_rn(w1 * qs);
            int q2 = __float2int_rn(w2 * qs);
            int q3 = __float2int_rn(w3 * qs);
            isum += (q0 + q1) + (q2 + q3);
            int h0 = (q0 + 128) >> 8, h1 = (q1 + 128) >> 8;
            int h2 = (q2 + 128) >> 8, h3 = (q3 + 128) >> 8;
            uint32_t hp = (uint32_t)h0 | ((uint32_t)h1 << 8) |
                          ((uint32_t)h2 << 16) | ((uint32_t)h3 << 24);
            uint32_t lp = (uint32_t)((q0 - (h0 << 8)) & 255) |
                          ((uint32_t)((q1 - (h1 << 8)) & 255) << 8) |
                          ((uint32_t)((q2 - (h2 << 8)) & 255) << 16) |
                          ((uint32_t)((q3 - (h3 << 8)) & 255) << 24);
            *reinterpret_cast<uint32_t*>(a0 + u * 4) = hp;
            *reinterpret_cast<uint32_t*>(a0 + ALIMB + u * 4) = lp;
        }
    };

    if (producer) {
        issueB(0, 0);
        buildA(0, 0);
        cpasync_wait0();
    }
    __syncthreads();

    for (int p = 0; p < NCH; ++p) {
        int buf = p & 1;
        if (producer) {
            if (p + 1 < NCH) {
                issueB(p + 1, buf ^ 1);
                buildA(p + 1, buf ^ 1);
                cpasync_wait0();
            }
        } else {
            const char* aB = sm + A_OFF(buf);
            const char* bB = sm + B_OFF(buf);
#pragma unroll
            for (int kst = 0; kst < 2; ++kst) {
                uint32_t af[2][2][4];
#pragma unroll
                for (int mt = 0; mt < 2; ++mt) {
#pragma unroll
                    for (int limb = 0; limb < 2; ++limb) {
                        const char* ap = aB + limb * ALIMB +
                                         (rg * 32 + mt * 16 + gid) * 80 + kst * 32 + tid4 * 4;
                        af[mt][limb][0] = *reinterpret_cast<const uint32_t*>(ap);
                        af[mt][limb][1] = *reinterpret_cast<const uint32_t*>(ap + 640);
                        af[mt][limb][2] = *reinterpret_cast<const uint32_t*>(ap + 16);
                        af[mt][limb][3] = *reinterpret_cast<const uint32_t*>(ap + 656);
                    }
                }
#pragma unroll
                for (int np = 0; np < 8; ++np) {
                    const char* bp = bB + (cg * 64 + np * 8 + gid) * 144 + kst * 32 + tid4 * 4;
                    uint32_t bh[2], bl[2];
                    bh[0] = *reinterpret_cast<const uint32_t*>(bp);
                    bh[1] = *reinterpret_cast<const uint32_t*>(bp + 16);
                    bl[0] = *reinterpret_cast<const uint32_t*>(bp + BLIMB);
                    bl[1] = *reinterpret_cast<const uint32_t*>(bp + BLIMB + 16);
#pragma unroll
                    for (int mt = 0; mt < 2; ++mt) {
                        imma(ahh[mt][np], af[mt][0], bh);
                        imma(amid[mt][np], af[mt][0], bl);
                        imma(amid[mt][np], af[mt][1], bh);
                    }
                }
            }
        }
        __syncthreads();
    }

    float* Zs = reinterpret_cast<float*>(sm + SM_ZS);
    if (producer) Zs[pt] = (float)isum;
    __syncthreads();

    if (!producer) {
        const float* coefS = reinterpret_cast<const float*>(sm + SM_COEF);
#pragma unroll
        for (int mt = 0; mt < 2; ++mt) {
            int r0 = rg * 32 + mt * 16 + gid;
            float rz0 = 1.0f / Zs[r0];
            float rz1 = 1.0f / Zs[r0 + 8];
            float* row0 = out + (size_t)(i0 + r0) * DIM + h * 128 + cg * 64 + tid4 * 2;
            float* row1 = row0 + (size_t)8 * DIM;
#pragma unroll
            for (int np = 0; np < 8; ++np) {
                float2 cf = *reinterpret_cast<const float2*>(coefS + cg * 64 + np * 8 + tid4 * 2);
                const int* chh = ahh[mt][np];
                const int* cmd = amid[mt][np];
                float v0 = fmaf(65536.0f, (float)chh[0], 256.0f * (float)cmd[0]);
                float v1 = fmaf(65536.0f, (float)chh[1], 256.0f * (float)cmd[1]);
                float v2 = fmaf(65536.0f, (float)chh[2], 256.0f * (float)cmd[2]);
                float v3 = fmaf(65536.0f, (float)chh[3], 256.0f * (float)cmd[3]);
                float2 o0 = make_float2(elu1(v0 * cf.x * rz0), elu1(v1 * cf.y * rz0));
                float2 o1 = make_float2(elu1(v2 * cf.x * rz1), elu1(v3 * cf.y * rz1));
                *reinterpret_cast<float2*>(row0 + np * 8) = o0;
                *reinterpret_cast<float2*>(row1 + np * 8) = o1;
            }
        }
    }
}

// ================= host orchestration =================
extern "C" void kernel_launch(void* const* d_in, const int* in_sizes, int n_in,
                              void* d_out, int out_size) {
    const float* V   = (const float*)d_in[0];
    const int*   adj = (const int*)d_in[1];
    const float* W1  = (const float*)d_in[2];
    const float* as1 = (const float*)d_in[3];
    const float* ad1 = (const float*)d_in[4];
    const float* W2  = (const float*)d_in[5];
    const float* as2 = (const float*)d_in[6];
    const float* ad2 = (const float*)d_in[7];
    float* out = (float*)d_out;

    float *Wh, *H, *s, *d, *colmax;
    float4* EEpG;
    float2* FFp;
    uint8_t *Bh8, *Bl8;
    uint32_t* adjP;
    cudaGetSymbolAddress((void**)&Wh, g_Wh);
    cudaGetSymbolAddress((void**)&H, g_H);
    cudaGetSymbolAddress((void**)&s, g_s);
    cudaGetSymbolAddress((void**)&d, g_d);
    cudaGetSymbolAddress((void**)&EEpG, g_EEpG);
    cudaGetSymbolAddress((void**)&FFp, g_FFp);
    cudaGetSymbolAddress((void**)&Bh8, g_Bh8);
    cudaGetSymbolAddress((void**)&Bl8, g_Bl8);
    cudaGetSymbolAddress((void**)&colmax, g_colmax);
    cudaGetSymbolAddress((void**)&adjP, g_adjP);

    cudaFuncSetAttribute(gat_imma_kernel,
                         cudaFuncAttributeMaxDynamicSharedMemorySize, GAT_SMEM);

    pack_adj_kernel<<<8192, 256>>>(adj, adjP);

    // ---- layer 1 ----
    cudaMemsetAsync(colmax, 0, (DIM + 2) * sizeof(float));
    gemm_wh_kernel<<<NN / GW_BM, GW_NT>>>(V, W1, as1, ad1, Wh, s, d, colmax);
    trans_quant_kernel<<<dim3(128, 4), 256>>>(Wh, colmax, Bh8, Bl8);
    factors_kernel<<<NN / 256, 256>>>(s, d, colmax, EEpG, FFp);
    gat_imma_kernel<<<128, GAT_NT, GAT_SMEM>>>(adjP, Bh8, Bl8, EEpG, FFp, colmax, H);

    // ---- layer 2 ----
    cudaMemsetAsync(colmax, 0, (DIM + 2) * sizeof(float));
    gemm_wh_kernel<<<NN / GW_BM, GW_NT>>>(H, W2, as2, ad2, Wh, s, d, colmax);
    trans_quant_kernel<<<dim3(128, 4), 256>>>(Wh, colmax, Bh8, Bl8);
    factors_kernel<<<NN / 256, 256>>>(s, d, colmax, EEpG, FFp);
    gat_imma_kernel<<<128, GAT_NT, GAT_SMEM>>>(adjP, Bh8, Bl8, EEpG, FFp, colmax, out);
}